// round 8
// baseline (speedup 1.0000x reference)
#include <cuda_runtime.h>
#include <cstdint>

#define B 32
#define T_IN 512
#define T_OUT 2048
#define ADIM 384
#define PDIM 4
#define NROWS (B * T_OUT)
#define NV (ADIM / 4)          // 96 float4 per row
#define CHUNK 64               // contiguous rows per block (divides T_OUT)
#define GRID_MAIN (NROWS / CHUNK)   // 1024 blocks

__device__ __forceinline__ float4 row_embed(const float4 pt, const float et,
                                            const float4 w0, const float4 w1,
                                            const float4 w2, const float4 w3,
                                            const float4 ewv, const float4 bias) {
    float4 r;
    r.x = fmaf(et, ewv.x, bias.x);
    r.y = fmaf(et, ewv.y, bias.y);
    r.z = fmaf(et, ewv.z, bias.z);
    r.w = fmaf(et, ewv.w, bias.w);
    r.x = fmaf(pt.x, w0.x, fmaf(pt.y, w0.y, fmaf(pt.z, w0.z, fmaf(pt.w, w0.w, r.x))));
    r.y = fmaf(pt.x, w1.x, fmaf(pt.y, w1.y, fmaf(pt.z, w1.z, fmaf(pt.w, w1.w, r.y))));
    r.z = fmaf(pt.x, w2.x, fmaf(pt.y, w2.y, fmaf(pt.z, w2.z, fmaf(pt.w, w2.w, r.z))));
    r.w = fmaf(pt.x, w3.x, fmaf(pt.y, w3.y, fmaf(pt.z, w3.z, fmaf(pt.w, w3.w, r.w))));
    return r;
}

// -------- Fused kernel: per-block duration scan + gather + embeds --------
// Integer inputs may be int32 or int64 (jax default config downcasts int64 ->
// int32). Durations are in [1,4]; for little-endian int64 odd words are 0.
__global__ void __launch_bounds__(NV * 4)
fused_kernel(const float* __restrict__ hs,
             const int*   __restrict__ dur32,
             const int*   __restrict__ ilen32,
             const float* __restrict__ pitch_target,
             const float* __restrict__ energy_target,
             const float* __restrict__ pitch_w,   // [ADIM, 4]
             const float* __restrict__ pitch_b,   // [ADIM]
             const float* __restrict__ energy_w,  // [ADIM]
             const float* __restrict__ energy_b,  // [ADIM]
             float* __restrict__ out) {
    __shared__ int    s_cum[T_IN];
    __shared__ int    s_idx[CHUNK];
    __shared__ float4 s_pt[CHUNK];
    __shared__ float  s_et[CHUNK];

    const int tx = threadIdx.x;                 // 0..95 (channel group)
    const int ty = threadIdx.y;                 // 0..3
    const int tid = ty * NV + tx;               // 0..383
    const int row0 = blockIdx.x * CHUNK;
    const int bb = row0 / T_OUT;                // batch for this block
    const int t0 = row0 - bb * T_OUT;           // first within-batch frame
    const int a = tx * 4;

    // ---- Phase 1 (parallel): durations -> s_cum, et/pt -> smem ----
    const bool is64 = (dur32[1] == 0);
    const int L = is64 ? ilen32[2 * bb] : ilen32[bb];
    {
        const int base = bb * T_IN;
        int e = tid;                            // 0..383
        s_cum[e] = (e < L) ? (is64 ? dur32[2 * (base + e)] : dur32[base + e]) : 0;
        if (tid < T_IN - 384) {                 // 128 threads cover 384..511
            e = tid + 384;
            s_cum[e] = (e < L) ? (is64 ? dur32[2 * (base + e)] : dur32[base + e]) : 0;
        }
    }
    if (tid < CHUNK) {
        s_et[tid] = energy_target[row0 + tid];
    } else if (tid < CHUNK + 4 * CHUNK) {       // 64..319 -> 256 pt words
        const int j = tid - CHUNK;
        reinterpret_cast<float*>(s_pt)[j] = pitch_target[row0 * PDIM + j];
    }
    __syncthreads();

    // ---- Phase 2: warp 0 scans 512 values (16/lane + shuffle scan) ----
    if (tid < 32) {
        const int base = tid * 16;
        int v[16];
        int s = 0;
        #pragma unroll
        for (int k = 0; k < 16; k++) { v[k] = s_cum[base + k]; s += v[k]; }
        int p = s;
        #pragma unroll
        for (int off = 1; off < 32; off <<= 1) {
            int q = __shfl_up_sync(0xffffffffu, p, off);
            if (tid >= off) p += q;
        }
        p -= s;                                 // exclusive prefix of lane sums
        #pragma unroll
        for (int k = 0; k < 16; k++) { p += v[k]; s_cum[base + k] = p; }
    }
    __syncthreads();

    // ---- torch semantics: if total == 0, valid positions get duration 1 ----
    if (s_cum[T_IN - 1] == 0) {
        s_cum[tid] = min(tid + 1, L);
        if (tid < T_IN - 384) s_cum[tid + 384] = min(tid + 384 + 1, L);
        __syncthreads();
    }
    const int total = s_cum[T_IN - 1];

    // ---- Phase 3: 64 threads binary-search their output frames ----
    if (tid < CHUNK) {
        const int to = t0 + tid;
        int lo = 0, hi = T_IN;
        while (lo < hi) {
            int mid = (lo + hi) >> 1;
            if (s_cum[mid] <= to) lo = mid + 1; else hi = mid;
        }
        s_idx[tid] = (to < total) ? min(lo, T_IN - 1) : -1;
    }

    // ---- Weights/biases into registers (independent of staging) ----
    const float4 w0 = *reinterpret_cast<const float4*>(pitch_w + (a + 0) * 4);
    const float4 w1 = *reinterpret_cast<const float4*>(pitch_w + (a + 1) * 4);
    const float4 w2 = *reinterpret_cast<const float4*>(pitch_w + (a + 2) * 4);
    const float4 w3 = *reinterpret_cast<const float4*>(pitch_w + (a + 3) * 4);
    const float4 pbv = *reinterpret_cast<const float4*>(pitch_b + a);
    const float4 ewv = *reinterpret_cast<const float4*>(energy_w + a);
    const float4 ebv = *reinterpret_cast<const float4*>(energy_b + a);
    float4 bias;
    bias.x = pbv.x + ebv.x; bias.y = pbv.y + ebv.y;
    bias.z = pbv.z + ebv.z; bias.w = pbv.w + ebv.w;

    __syncthreads();

    const float* __restrict__ hsb = hs + (size_t)bb * T_IN * ADIM + a;
    float* __restrict__ outb = out + (size_t)row0 * ADIM + a;

    // ---- Steady state: 16 rows/thread, batches of 4 (4 gathers in flight) ----
    #pragma unroll
    for (int ii = 0; ii < CHUNK / 4; ii += 4) {
        const int lr0 = ii * 4 + ty;
        const int lr1 = lr0 + 4;
        const int lr2 = lr0 + 8;
        const int lr3 = lr0 + 12;
        const int i0 = s_idx[lr0];
        const int i1 = s_idx[lr1];
        const int i2 = s_idx[lr2];
        const int i3 = s_idx[lr3];

        float4 h0 = make_float4(0.f, 0.f, 0.f, 0.f);
        float4 h1 = make_float4(0.f, 0.f, 0.f, 0.f);
        float4 h2 = make_float4(0.f, 0.f, 0.f, 0.f);
        float4 h3 = make_float4(0.f, 0.f, 0.f, 0.f);
        if (i0 >= 0) h0 = __ldg(reinterpret_cast<const float4*>(hsb + (size_t)i0 * ADIM));
        if (i1 >= 0) h1 = __ldg(reinterpret_cast<const float4*>(hsb + (size_t)i1 * ADIM));
        if (i2 >= 0) h2 = __ldg(reinterpret_cast<const float4*>(hsb + (size_t)i2 * ADIM));
        if (i3 >= 0) h3 = __ldg(reinterpret_cast<const float4*>(hsb + (size_t)i3 * ADIM));

        float4 r0 = row_embed(s_pt[lr0], s_et[lr0], w0, w1, w2, w3, ewv, bias);
        float4 r1 = row_embed(s_pt[lr1], s_et[lr1], w0, w1, w2, w3, ewv, bias);
        float4 r2 = row_embed(s_pt[lr2], s_et[lr2], w0, w1, w2, w3, ewv, bias);
        float4 r3 = row_embed(s_pt[lr3], s_et[lr3], w0, w1, w2, w3, ewv, bias);
        r0.x += h0.x; r0.y += h0.y; r0.z += h0.z; r0.w += h0.w;
        r1.x += h1.x; r1.y += h1.y; r1.z += h1.z; r1.w += h1.w;
        r2.x += h2.x; r2.y += h2.y; r2.z += h2.z; r2.w += h2.w;
        r3.x += h3.x; r3.y += h3.y; r3.z += h3.z; r3.w += h3.w;

        __stcs(reinterpret_cast<float4*>(outb + (size_t)lr0 * ADIM), r0);
        __stcs(reinterpret_cast<float4*>(outb + (size_t)lr1 * ADIM), r1);
        __stcs(reinterpret_cast<float4*>(outb + (size_t)lr2 * ADIM), r2);
        __stcs(reinterpret_cast<float4*>(outb + (size_t)lr3 * ADIM), r3);
    }
}

extern "C" void kernel_launch(void* const* d_in, const int* in_sizes, int n_in,
                              void* d_out, int out_size) {
    const float* hs   = (const float*)d_in[0];
    const int*   dur  = (const int*)d_in[1];   // int32 or int64 (probed in-kernel)
    const int*   ilen = (const int*)d_in[2];
    const float* pt   = (const float*)d_in[3];
    const float* et   = (const float*)d_in[4];
    // d_in[5], d_in[6]: duration_mask / variance_mask (unused, all false)
    const float* pw   = (const float*)d_in[7];
    const float* pb   = (const float*)d_in[8];
    const float* ew   = (const float*)d_in[9];
    const float* eb   = (const float*)d_in[10];
    float*       out  = (float*)d_out;

    dim3 blk(NV, 4);                            // 96 x 4 = 384 threads
    fused_kernel<<<GRID_MAIN, blk>>>(hs, dur, ilen, pt, et, pw, pb, ew, eb, out);
}

// round 9
// speedup vs baseline: 1.0694x; 1.0694x over previous
#include <cuda_runtime.h>
#include <cstdint>

#define B 32
#define T_IN 512
#define T_OUT 2048
#define ADIM 384
#define PDIM 4
#define NROWS (B * T_OUT)
#define NV (ADIM / 4)          // 96 float4 per row
#define CHUNK 128              // contiguous rows per block (divides T_OUT)
#define GRID_MAIN (NROWS / CHUNK)   // 512 blocks

__device__ __forceinline__ float4 row_embed(const float4 pt, const float et,
                                            const float4 w0, const float4 w1,
                                            const float4 w2, const float4 w3,
                                            const float4 ewv, const float4 bias) {
    float4 r;
    r.x = fmaf(et, ewv.x, bias.x);
    r.y = fmaf(et, ewv.y, bias.y);
    r.z = fmaf(et, ewv.z, bias.z);
    r.w = fmaf(et, ewv.w, bias.w);
    r.x = fmaf(pt.x, w0.x, fmaf(pt.y, w0.y, fmaf(pt.z, w0.z, fmaf(pt.w, w0.w, r.x))));
    r.y = fmaf(pt.x, w1.x, fmaf(pt.y, w1.y, fmaf(pt.z, w1.z, fmaf(pt.w, w1.w, r.y))));
    r.z = fmaf(pt.x, w2.x, fmaf(pt.y, w2.y, fmaf(pt.z, w2.z, fmaf(pt.w, w2.w, r.z))));
    r.w = fmaf(pt.x, w3.x, fmaf(pt.y, w3.y, fmaf(pt.z, w3.z, fmaf(pt.w, w3.w, r.w))));
    return r;
}

// -------- Fused kernel: per-block duration scan + gather + embeds --------
// Integer inputs may be int32 or int64 (jax default config downcasts int64 ->
// int32). Durations are in [1,4]; for little-endian int64 odd words are 0.
__global__ void __launch_bounds__(NV * 4)
fused_kernel(const float* __restrict__ hs,
             const int*   __restrict__ dur32,
             const int*   __restrict__ ilen32,
             const float* __restrict__ pitch_target,
             const float* __restrict__ energy_target,
             const float* __restrict__ pitch_w,   // [ADIM, 4]
             const float* __restrict__ pitch_b,   // [ADIM]
             const float* __restrict__ energy_w,  // [ADIM]
             const float* __restrict__ energy_b,  // [ADIM]
             float* __restrict__ out) {
    __shared__ int    s_cum[T_IN];
    __shared__ int    s_idx[CHUNK];
    __shared__ float4 s_pt[CHUNK];
    __shared__ float  s_et[CHUNK];

    const int tx = threadIdx.x;                 // 0..95 (channel group)
    const int ty = threadIdx.y;                 // 0..3
    const int tid = ty * NV + tx;               // 0..383
    const int row0 = blockIdx.x * CHUNK;
    const int bb = row0 / T_OUT;                // batch for this block
    const int t0 = row0 - bb * T_OUT;           // first within-batch frame
    const int a = tx * 4;

    // ---- Phase 1 (parallel): durations + et + pt staged before one barrier ----
    const bool is64 = (dur32[1] == 0);
    const int L = is64 ? ilen32[2 * bb] : ilen32[bb];
    {
        const int base = bb * T_IN;
        int e = tid;                            // 0..383
        s_cum[e] = (e < L) ? (is64 ? dur32[2 * (base + e)] : dur32[base + e]) : 0;
        if (tid < T_IN - 384) {                 // 128 threads cover 384..511
            e = tid + 384;
            s_cum[e] = (e < L) ? (is64 ? dur32[2 * (base + e)] : dur32[base + e]) : 0;
        }
    }
    if (tid < CHUNK) {
        s_et[tid] = energy_target[row0 + tid];
    }
    {
        // 512 pt words over 384 threads: word tid, plus tid+384 for tid<128.
        float* s_ptf = reinterpret_cast<float*>(s_pt);
        s_ptf[tid] = pitch_target[row0 * PDIM + tid];
        if (tid < 4 * CHUNK - 384) {
            s_ptf[tid + 384] = pitch_target[row0 * PDIM + tid + 384];
        }
    }
    __syncthreads();

    // ---- Phase 2: warp 0 scans 512 values (16/lane + shuffle scan) ----
    if (tid < 32) {
        const int base = tid * 16;
        int v[16];
        int s = 0;
        #pragma unroll
        for (int k = 0; k < 16; k++) { v[k] = s_cum[base + k]; s += v[k]; }
        int p = s;
        #pragma unroll
        for (int off = 1; off < 32; off <<= 1) {
            int q = __shfl_up_sync(0xffffffffu, p, off);
            if (tid >= off) p += q;
        }
        p -= s;                                 // exclusive prefix of lane sums
        #pragma unroll
        for (int k = 0; k < 16; k++) { p += v[k]; s_cum[base + k] = p; }
    }
    __syncthreads();

    // ---- torch semantics: if total == 0, valid positions get duration 1 ----
    if (s_cum[T_IN - 1] == 0) {
        s_cum[tid] = min(tid + 1, L);
        if (tid < T_IN - 384) s_cum[tid + 384] = min(tid + 384 + 1, L);
        __syncthreads();
    }
    const int total = s_cum[T_IN - 1];

    // ---- Phase 3: 128 threads binary-search their output frames ----
    if (tid < CHUNK) {
        const int to = t0 + tid;
        int lo = 0, hi = T_IN;
        while (lo < hi) {
            int mid = (lo + hi) >> 1;
            if (s_cum[mid] <= to) lo = mid + 1; else hi = mid;
        }
        s_idx[tid] = (to < total) ? min(lo, T_IN - 1) : -1;
    }

    // ---- Weights/biases into registers (independent of staging) ----
    const float4 w0 = *reinterpret_cast<const float4*>(pitch_w + (a + 0) * 4);
    const float4 w1 = *reinterpret_cast<const float4*>(pitch_w + (a + 1) * 4);
    const float4 w2 = *reinterpret_cast<const float4*>(pitch_w + (a + 2) * 4);
    const float4 w3 = *reinterpret_cast<const float4*>(pitch_w + (a + 3) * 4);
    const float4 pbv = *reinterpret_cast<const float4*>(pitch_b + a);
    const float4 ewv = *reinterpret_cast<const float4*>(energy_w + a);
    const float4 ebv = *reinterpret_cast<const float4*>(energy_b + a);
    float4 bias;
    bias.x = pbv.x + ebv.x; bias.y = pbv.y + ebv.y;
    bias.z = pbv.z + ebv.z; bias.w = pbv.w + ebv.w;

    __syncthreads();

    const float* __restrict__ hsb = hs + (size_t)bb * T_IN * ADIM + a;
    float* __restrict__ outb = out + (size_t)row0 * ADIM + a;

    // ---- Steady state: 32 rows/thread, batches of 2 (2 gathers in flight) ----
    #pragma unroll
    for (int ii = 0; ii < CHUNK / 4; ii += 2) {
        const int lr0 = ii * 4 + ty;
        const int lr1 = lr0 + 4;
        const int i0 = s_idx[lr0];
        const int i1 = s_idx[lr1];

        float4 h0 = make_float4(0.f, 0.f, 0.f, 0.f);
        float4 h1 = make_float4(0.f, 0.f, 0.f, 0.f);
        if (i0 >= 0) h0 = __ldg(reinterpret_cast<const float4*>(hsb + (size_t)i0 * ADIM));
        if (i1 >= 0) h1 = __ldg(reinterpret_cast<const float4*>(hsb + (size_t)i1 * ADIM));

        float4 r0 = row_embed(s_pt[lr0], s_et[lr0], w0, w1, w2, w3, ewv, bias);
        float4 r1 = row_embed(s_pt[lr1], s_et[lr1], w0, w1, w2, w3, ewv, bias);
        r0.x += h0.x; r0.y += h0.y; r0.z += h0.z; r0.w += h0.w;
        r1.x += h1.x; r1.y += h1.y; r1.z += h1.z; r1.w += h1.w;

        __stcs(reinterpret_cast<float4*>(outb + (size_t)lr0 * ADIM), r0);
        __stcs(reinterpret_cast<float4*>(outb + (size_t)lr1 * ADIM), r1);
    }
}

extern "C" void kernel_launch(void* const* d_in, const int* in_sizes, int n_in,
                              void* d_out, int out_size) {
    const float* hs   = (const float*)d_in[0];
    const int*   dur  = (const int*)d_in[1];   // int32 or int64 (probed in-kernel)
    const int*   ilen = (const int*)d_in[2];
    const float* pt   = (const float*)d_in[3];
    const float* et   = (const float*)d_in[4];
    // d_in[5], d_in[6]: duration_mask / variance_mask (unused, all false)
    const float* pw   = (const float*)d_in[7];
    const float* pb   = (const float*)d_in[8];
    const float* ew   = (const float*)d_in[9];
    const float* eb   = (const float*)d_in[10];
    float*       out  = (float*)d_out;

    dim3 blk(NV, 4);                            // 96 x 4 = 384 threads
    fused_kernel<<<GRID_MAIN, blk>>>(hs, dur, ilen, pt, et, pw, pb, ew, eb, out);
}